// round 16
// baseline (speedup 1.0000x reference)
#include <cuda_runtime.h>
#include <cuda_fp16.h>
#include <cstdint>

// ----------------------------------------------------------------------------
// GCN: agg1 = relu(Ahat (x@W1) + b1); h2 = agg1 @ W2;
//      pool = segment_max(relu(Ahat h2 + b2), batch); out = pool @ Wfc + bfc
// R16 = R15 + GEMM1 keeps ALL of W1h (64KB fp16) resident in smem: B loaded
// once per block, zero cp.async waits in the K loop, 1 sync per tile.
// A staged fp32->fp16 via register-pipelined LDG->STS (2 tiles ahead).
// Bucketed edges (single fill pass); cnt zeroed by k_dis, pool by k_fc.
// ----------------------------------------------------------------------------

#define N_NODES 50000
#define N_EDGES 800000
#define N_GRAPHS 128
#define IN_DIM 256
#define H1 128
#define H2 64
#define OUT_DIM 10
#define CAP 192

__device__ int    g_cnt[N_NODES];        // zero at load; re-zeroed by k_dis
__device__ int    g_deg[N_NODES];
__device__ float  g_dis[N_NODES];
__device__ int    g_crow[(size_t)N_NODES * CAP];
__device__ __half g_W1h[H1 * IN_DIM];    // W1 transposed [n][k], fp16
__device__ __half g_W2h[H2 * H1];        // W2 transposed [n][k], fp16
__device__ __half g_h1[(size_t)N_NODES * H1];
__device__ __half g_agg1[(size_t)N_NODES * H1];
__device__ __half g_h2[(size_t)N_NODES * H2];
__device__ float  g_pool[N_GRAPHS * H2]; // zero at load; re-zeroed by k_fc

// ---------------------------------------------------------------- utils
#define MMA_F16(d, a, b)                                                      \
    asm volatile(                                                             \
        "mma.sync.aligned.m16n8k16.row.col.f32.f16.f16.f32 "                  \
        "{%0,%1,%2,%3},{%4,%5,%6,%7},{%8,%9},{%0,%1,%2,%3};"                  \
        : "+f"((d)[0]), "+f"((d)[1]), "+f"((d)[2]), "+f"((d)[3])              \
        : "r"((a)[0]), "r"((a)[1]), "r"((a)[2]), "r"((a)[3]),                 \
          "r"((b)[0]), "r"((b)[1]))

__device__ __forceinline__ void cp16(uint32_t saddr, const void* gaddr, int sz) {
    asm volatile("cp.async.cg.shared.global [%0], [%1], 16, %2;"
                 :: "r"(saddr), "l"(gaddr), "r"(sz));
}

__device__ __forceinline__ float4 ldh4(const __half* p) {
    uint2 u = *(const uint2*)p;
    float2 a = __half22float2(*(__half2*)&u.x);
    float2 b = __half22float2(*(__half2*)&u.y);
    return make_float4(a.x, a.y, b.x, b.y);
}

// ---------------------------------------------------------------- weight prep (side stream, before GEMM1)
__global__ void k_prepW(const float* __restrict__ W1, const float* __restrict__ W2,
                        __half* __restrict__ W1h, __half* __restrict__ W2h)
{
    int i = blockIdx.x * blockDim.x + threadIdx.x;
    if (i < IN_DIM * H1) {              // W1[k][n] -> W1h[n][k]
        int k = i >> 7, n = i & 127;
        W1h[n * IN_DIM + k] = __float2half(W1[i]);
    }
    if (i < H1 * H2) {                  // W2[k][n] -> W2h[n][k]
        int k = i >> 6, n = i & 63;
        W2h[n * H1 + k] = __float2half(W2[i]);
    }
}

// ---------------------------------------------------------------- bucket fill
__global__ void k_fill(const int* __restrict__ row, const int* __restrict__ col,
                       int* __restrict__ cnt, int* __restrict__ crow)
{
    int i = blockIdx.x * blockDim.x + threadIdx.x;
    if (i * 4 >= N_EDGES) return;
    int4 r = *(const int4*)(row + i * 4);
    int4 c = *(const int4*)(col + i * 4);
    int p0 = atomicAdd(&cnt[c.x], 1);
    int p1 = atomicAdd(&cnt[c.y], 1);
    int p2 = atomicAdd(&cnt[c.z], 1);
    int p3 = atomicAdd(&cnt[c.w], 1);
    crow[(size_t)c.x * CAP + p0] = r.x;
    crow[(size_t)c.y * CAP + p1] = r.y;
    crow[(size_t)c.z * CAP + p2] = r.z;
    crow[(size_t)c.w * CAP + p3] = r.w;
}

__global__ void k_dis(int* __restrict__ cnt, int* __restrict__ deg,
                      float* __restrict__ dis)
{
    int i = blockIdx.x * blockDim.x + threadIdx.x;
    if (i < N_NODES) {
        int v = cnt[i];
        deg[i] = v;
        dis[i] = rsqrtf((float)(v + 1));
        cnt[i] = 0;
    }
}

// ---------------------------------------------------------------- GEMM1 (fp16 mma; whole W1h resident in smem)
// 512 thr, 16 warps (4x4), warp tile 32x32. K=256 in 8 tiles of 32.
#define G1_SA 40                      // A smem stride (halves)
#define G1_SB 264                     // B smem stride (256 + 8 halves)
#define G1_ABUF (2 * 128 * G1_SA)     // 10240 halves
#define G1_SMEM ((G1_ABUF + 128 * G1_SB) * 2)   // 88064 bytes

__global__ void __launch_bounds__(512)
k_gemm1_f16(const float* __restrict__ A, const __half* __restrict__ W1h,
            __half* __restrict__ C, int M)
{
    extern __shared__ __half sm1[];
    __half* As = sm1;                  // [2][128 * G1_SA]
    __half* Bs = sm1 + G1_ABUF;        // [128][G1_SB]

    const int tid = threadIdx.x, wid = tid >> 5, lane = tid & 31;
    const int wm = wid % 4, wn = wid / 4;
    const int g = lane >> 2, tig = lane & 3;
    const int m0 = blockIdx.x * 128;

    // --- B: load ALL of W1h once (128 rows x 256 halves = 2048 x 16B) ---
#pragma unroll
    for (int i = tid; i < 128 * 32; i += 512) {
        int n = i >> 5, c8 = i & 31;
        cp16((uint32_t)__cvta_generic_to_shared(&Bs[n * G1_SB + c8 * 8]),
             W1h + n * IN_DIM + c8 * 8, 16);
    }
    asm volatile("cp.async.commit_group;");

    // --- A staging: 4 threads per row, 8 fp32 each ---
    const int ar = tid >> 2;
    const int af4 = (tid & 3) * 2;
    const bool arow_ok = (m0 + ar < M);

    float4 ra0, ra1;
    auto ldA = [&](int t) {
        if (arow_ok) {
            const float* src = A + (size_t)(m0 + ar) * IN_DIM + t * 32 + af4 * 4;
            ra0 = *(const float4*)src;
            ra1 = *(const float4*)(src + 4);
        } else {
            ra0 = make_float4(0.f, 0.f, 0.f, 0.f);
            ra1 = ra0;
        }
    };
    auto stA = [&](int buf) {
        __half2* dst = (__half2*)&As[buf * 128 * G1_SA + ar * G1_SA + af4 * 4];
        dst[0] = __floats2half2_rn(ra0.x, ra0.y);
        dst[1] = __floats2half2_rn(ra0.z, ra0.w);
        dst[2] = __floats2half2_rn(ra1.x, ra1.y);
        dst[3] = __floats2half2_rn(ra1.z, ra1.w);
    };

    float acc[2][4][4];
#pragma unroll
    for (int i = 0; i < 2; i++)
#pragma unroll
        for (int j = 0; j < 4; j++)
#pragma unroll
            for (int q = 0; q < 4; q++) acc[i][j][q] = 0.f;

    // prologue
    ldA(0);
    stA(0);
    ldA(1);
    asm volatile("cp.async.wait_group 0;");
    __syncthreads();

#pragma unroll
    for (int t = 0; t < 8; t++) {
        const int cur = t & 1, nxt = cur ^ 1;
        const __half* Ab = &As[cur * 128 * G1_SA];
#pragma unroll
        for (int kk = 0; kk < 2; kk++) {
            uint32_t af[2][4], bf[4][2];
#pragma unroll
            for (int mt = 0; mt < 2; mt++) {
                int r = wm * 32 + mt * 16;
                af[mt][0] = *(const uint32_t*)&Ab[(r + g)     * G1_SA + kk * 16 + 2 * tig];
                af[mt][1] = *(const uint32_t*)&Ab[(r + g + 8) * G1_SA + kk * 16 + 2 * tig];
                af[mt][2] = *(const uint32_t*)&Ab[(r + g)     * G1_SA + kk * 16 + 8 + 2 * tig];
                af[mt][3] = *(const uint32_t*)&Ab[(r + g + 8) * G1_SA + kk * 16 + 8 + 2 * tig];
            }
#pragma unroll
            for (int nt = 0; nt < 4; nt++) {
                int c = wn * 32 + nt * 8;
                bf[nt][0] = *(const uint32_t*)&Bs[(c + g) * G1_SB + t * 32 + kk * 16 + 2 * tig];
                bf[nt][1] = *(const uint32_t*)&Bs[(c + g) * G1_SB + t * 32 + kk * 16 + 8 + 2 * tig];
            }
#pragma unroll
            for (int mt = 0; mt < 2; mt++)
#pragma unroll
                for (int nt = 0; nt < 4; nt++)
                    MMA_F16(acc[mt][nt], af[mt], bf[nt]);
        }
        if (t < 7) {
            stA(nxt);                    // write buffer nxt (disjoint from cur)
            if (t < 6) ldA(t + 2);       // prefetch 2 tiles ahead
            __syncthreads();             // one sync per tile
        }
    }

#pragma unroll
    for (int mt = 0; mt < 2; mt++) {
        int r0 = m0 + wm * 32 + mt * 16 + g;
#pragma unroll
        for (int nt = 0; nt < 4; nt++) {
            int c = wn * 32 + nt * 8 + 2 * tig;
            if (r0 < M)
                *(__half2*)(C + (size_t)r0 * H1 + c) =
                    __floats2half2_rn(acc[mt][nt][0], acc[mt][nt][1]);
            if (r0 + 8 < M)
                *(__half2*)(C + (size_t)(r0 + 8) * H1 + c) =
                    __floats2half2_rn(acc[mt][nt][2], acc[mt][nt][3]);
        }
    }
}

// ---------------------------------------------------------------- GEMM2 (fp16 mma; W2h via cp.async)
#define G2_SA 136
#define G2_SB 136
#define G2_SMEM ((128 * G2_SA + 64 * G2_SB) * 2)

__global__ void __launch_bounds__(256)
k_gemm2_f16(const __half* __restrict__ A, const __half* __restrict__ W2h,
            __half* __restrict__ C, int M)
{
    extern __shared__ __half sm[];
    __half* As  = sm;
    __half* Bs2 = sm + 128 * G2_SA;

    const int tid = threadIdx.x, wid = tid >> 5, lane = tid & 31;
    const int wm = wid % 4, wn = wid / 4;
    const int g = lane >> 2, tig = lane & 3;
    const int m0 = blockIdx.x * 128;

#pragma unroll
    for (int i = tid; i < 128 * 16; i += 256) {
        int r = i / 16, c8 = i % 16;
        cp16((uint32_t)__cvta_generic_to_shared(&As[r * G2_SA + c8 * 8]),
             A + (size_t)(m0 + r) * 128 + c8 * 8,
             (m0 + r < M) ? 16 : 0);
    }
#pragma unroll
    for (int i = tid; i < 64 * 16; i += 256) {
        int n = i / 16, c8 = i % 16;
        cp16((uint32_t)__cvta_generic_to_shared(&Bs2[n * G2_SB + c8 * 8]),
             W2h + n * H1 + c8 * 8, 16);
    }
    asm volatile("cp.async.commit_group;");
    asm volatile("cp.async.wait_group 0;");
    __syncthreads();

    float acc[2][4][4];
#pragma unroll
    for (int i = 0; i < 2; i++)
#pragma unroll
        for (int j = 0; j < 4; j++)
#pragma unroll
            for (int q = 0; q < 4; q++) acc[i][j][q] = 0.f;

#pragma unroll
    for (int kk = 0; kk < 8; kk++) {
        uint32_t af[2][4], bf[4][2];
#pragma unroll
        for (int mt = 0; mt < 2; mt++) {
            int r = wm * 32 + mt * 16;
            af[mt][0] = *(const uint32_t*)&As[(r + g)     * G2_SA + kk * 16 + 2 * tig];
            af[mt][1] = *(const uint32_t*)&As[(r + g + 8) * G2_SA + kk * 16 + 2 * tig];
            af[mt][2] = *(const uint32_t*)&As[(r + g)     * G2_SA + kk * 16 + 8 + 2 * tig];
            af[mt][3] = *(const uint32_t*)&As[(r + g + 8) * G2_SA + kk * 16 + 8 + 2 * tig];
        }
#pragma unroll
        for (int nt = 0; nt < 4; nt++) {
            int c = wn * 32 + nt * 8;
            bf[nt][0] = *(const uint32_t*)&Bs2[(c + g) * G2_SB + kk * 16 + 2 * tig];
            bf[nt][1] = *(const uint32_t*)&Bs2[(c + g) * G2_SB + kk * 16 + 8 + 2 * tig];
        }
#pragma unroll
        for (int mt = 0; mt < 2; mt++)
#pragma unroll
            for (int nt = 0; nt < 4; nt++)
                MMA_F16(acc[mt][nt], af[mt], bf[nt]);
    }

#pragma unroll
    for (int mt = 0; mt < 2; mt++) {
        int r0 = m0 + wm * 32 + mt * 16 + g;
#pragma unroll
        for (int nt = 0; nt < 4; nt++) {
            int c = wn * 32 + nt * 8 + 2 * tig;
            if (r0 < M)
                *(__half2*)(C + (size_t)r0 * 64 + c) =
                    __floats2half2_rn(acc[mt][nt][0], acc[mt][nt][1]);
            if (r0 + 8 < M)
                *(__half2*)(C + (size_t)(r0 + 8) * 64 + c) =
                    __floats2half2_rn(acc[mt][nt][2], acc[mt][nt][3]);
        }
    }
}

// ---------------------------------------------------------------- gather1 (+bias+relu); norm on the fly
__global__ void k_gather128(const __half* __restrict__ h, __half* __restrict__ agg,
                            const int* __restrict__ deg, const int* __restrict__ crow,
                            const float* __restrict__ dis, const float* __restrict__ bias)
{
    int node = (blockIdx.x * blockDim.x + threadIdx.x) >> 5;
    int lane = threadIdx.x & 31;
    if (node >= N_NODES) return;

    float dnode = dis[node];
    float dd = dnode * dnode;
    float4 acc = ldh4(h + (size_t)node * 128 + lane * 4);
    acc.x *= dd; acc.y *= dd; acc.z *= dd; acc.w *= dd;

    const int* base = crow + (size_t)node * CAP;
    int e = deg[node];
    int j = 0;
    for (; j + 7 < e; j += 8) {
        int p[8];
#pragma unroll
        for (int q = 0; q < 8; q++) p[q] = __ldg(base + j + q);
        float4 v[8];
        float nn[8];
#pragma unroll
        for (int q = 0; q < 8; q++) {
            v[q] = ldh4(h + (size_t)p[q] * 128 + lane * 4);
            nn[q] = __ldg(&dis[p[q]]) * dnode;
        }
#pragma unroll
        for (int q = 0; q < 8; q++) {
            acc.x = fmaf(v[q].x, nn[q], acc.x); acc.y = fmaf(v[q].y, nn[q], acc.y);
            acc.z = fmaf(v[q].z, nn[q], acc.z); acc.w = fmaf(v[q].w, nn[q], acc.w);
        }
    }
    for (; j + 3 < e; j += 4) {
        int p[4];
#pragma unroll
        for (int q = 0; q < 4; q++) p[q] = __ldg(base + j + q);
#pragma unroll
        for (int q = 0; q < 4; q++) {
            float4 v = ldh4(h + (size_t)p[q] * 128 + lane * 4);
            float n = __ldg(&dis[p[q]]) * dnode;
            acc.x = fmaf(v.x, n, acc.x); acc.y = fmaf(v.y, n, acc.y);
            acc.z = fmaf(v.z, n, acc.z); acc.w = fmaf(v.w, n, acc.w);
        }
    }
    for (; j < e; j++) {
        int p = __ldg(base + j);
        float n = __ldg(&dis[p]) * dnode;
        float4 v = ldh4(h + (size_t)p * 128 + lane * 4);
        acc.x = fmaf(v.x, n, acc.x); acc.y = fmaf(v.y, n, acc.y);
        acc.z = fmaf(v.z, n, acc.z); acc.w = fmaf(v.w, n, acc.w);
    }
    float4 bb = *(const float4*)(bias + lane * 4);
    acc.x = fmaxf(acc.x + bb.x, 0.f); acc.y = fmaxf(acc.y + bb.y, 0.f);
    acc.z = fmaxf(acc.z + bb.z, 0.f); acc.w = fmaxf(acc.w + bb.w, 0.f);
    uint2 st;
    *(__half2*)&st.x = __floats2half2_rn(acc.x, acc.y);
    *(__half2*)&st.y = __floats2half2_rn(acc.z, acc.w);
    *(uint2*)(agg + (size_t)node * 128 + lane * 4) = st;
}

// ---------------------------------------------------------------- gather2 + max-pool; norm on the fly
__global__ void k_gather64pool(const __half* __restrict__ h2,
                               const int* __restrict__ deg, const int* __restrict__ crow,
                               const float* __restrict__ dis, const float* __restrict__ b2,
                               const int* __restrict__ batch, float* __restrict__ pool)
{
    int node = (blockIdx.x * blockDim.x + threadIdx.x) >> 5;
    int lane = threadIdx.x & 31;
    if (node >= N_NODES) return;

    float dnode = dis[node];
    float dd = dnode * dnode;
    float2 acc = __half22float2(*(const __half2*)(h2 + (size_t)node * 64 + lane * 2));
    acc.x *= dd; acc.y *= dd;

    const int* base = crow + (size_t)node * CAP;
    int e = deg[node];
    int j = 0;
    for (; j + 7 < e; j += 8) {
        int p[8];
#pragma unroll
        for (int q = 0; q < 8; q++) p[q] = __ldg(base + j + q);
        float2 v[8];
        float nn[8];
#pragma unroll
        for (int q = 0; q < 8; q++) {
            v[q] = __half22float2(*(const __half2*)(h2 + (size_t)p[q] * 64 + lane * 2));
            nn[q] = __ldg(&dis[p[q]]) * dnode;
        }
#pragma unroll
        for (int q = 0; q < 8; q++) {
            acc.x = fmaf(v[q].x, nn[q], acc.x); acc.y = fmaf(v[q].y, nn[q], acc.y);
        }
    }
    for (; j + 3 < e; j += 4) {
        int p[4];
#pragma unroll
        for (int q = 0; q < 4; q++) p[q] = __ldg(base + j + q);
#pragma unroll
        for (int q = 0; q < 4; q++) {
            float2 v = __half22float2(*(const __half2*)(h2 + (size_t)p[q] * 64 + lane * 2));
            float n = __ldg(&dis[p[q]]) * dnode;
            acc.x = fmaf(v.x, n, acc.x); acc.y = fmaf(v.y, n, acc.y);
        }
    }
    for (; j < e; j++) {
        int p = __ldg(base + j);
        float n = __ldg(&dis[p]) * dnode;
        float2 v = __half22float2(*(const __half2*)(h2 + (size_t)p * 64 + lane * 2));
        acc.x = fmaf(v.x, n, acc.x); acc.y = fmaf(v.y, n, acc.y);
    }
    float2 bb = *(const float2*)(b2 + lane * 2);
    acc.x = fmaxf(acc.x + bb.x, 0.f);
    acc.y = fmaxf(acc.y + bb.y, 0.f);

    int gph = batch[node];
    atomicMax((unsigned int*)&pool[gph * H2 + lane * 2],     __float_as_uint(acc.x));
    atomicMax((unsigned int*)&pool[gph * H2 + lane * 2 + 1], __float_as_uint(acc.y));
}

// ---------------------------------------------------------------- final FC (re-zeroes pool after use)
__global__ void k_fc(float* __restrict__ pool, const float* __restrict__ Wfc,
                     const float* __restrict__ bfc, float* __restrict__ out)
{
    __shared__ float w[H2 * OUT_DIM];
    __shared__ float bb[OUT_DIM];
    int tid = threadIdx.x;
    for (int i = tid; i < H2 * OUT_DIM; i += blockDim.x) w[i] = Wfc[i];
    if (tid < OUT_DIM) bb[tid] = bfc[tid];
    __syncthreads();
    if (tid < N_GRAPHS) {
        float acc[OUT_DIM];
#pragma unroll
        for (int j = 0; j < OUT_DIM; j++) acc[j] = bb[j];
        for (int k = 0; k < H2; k++) {
            float g = pool[tid * H2 + k];
#pragma unroll
            for (int j = 0; j < OUT_DIM; j++) acc[j] = fmaf(g, w[k * OUT_DIM + j], acc[j]);
        }
#pragma unroll
        for (int j = 0; j < OUT_DIM; j++) out[tid * OUT_DIM + j] = acc[j];
    }
    __syncthreads();
    for (int i = tid; i < N_GRAPHS * H2; i += blockDim.x) pool[i] = 0.f;
}

// ---------------------------------------------------------------- launch
extern "C" void kernel_launch(void* const* d_in, const int* in_sizes, int n_in,
                              void* d_out, int out_size)
{
    const float* x    = (const float*)d_in[0];
    const int*   ei   = (const int*)d_in[1];
    const int*   batch= (const int*)d_in[2];
    const float* W1   = (const float*)d_in[3];
    const float* b1   = (const float*)d_in[4];
    const float* W2   = (const float*)d_in[5];
    const float* b2   = (const float*)d_in[6];
    const float* Wfc  = (const float*)d_in[7];
    const float* bfc  = (const float*)d_in[8];
    float* out = (float*)d_out;

    const int* row = ei;
    const int* col = ei + N_EDGES;

    int *cnt, *deg, *crow;
    float *dis, *pool;
    __half *h1, *agg1, *h2, *W1h, *W2h;
    cudaGetSymbolAddress((void**)&cnt,  g_cnt);
    cudaGetSymbolAddress((void**)&deg,  g_deg);
    cudaGetSymbolAddress((void**)&dis,  g_dis);
    cudaGetSymbolAddress((void**)&crow, g_crow);
    cudaGetSymbolAddress((void**)&W1h,  g_W1h);
    cudaGetSymbolAddress((void**)&W2h,  g_W2h);
    cudaGetSymbolAddress((void**)&h1,   g_h1);
    cudaGetSymbolAddress((void**)&agg1, g_agg1);
    cudaGetSymbolAddress((void**)&h2,   g_h2);
    cudaGetSymbolAddress((void**)&pool, g_pool);

    cudaFuncSetAttribute(k_gemm1_f16,
                         cudaFuncAttributeMaxDynamicSharedMemorySize, G1_SMEM);
    cudaFuncSetAttribute(k_gemm2_f16,
                         cudaFuncAttributeMaxDynamicSharedMemorySize, G2_SMEM);

    cudaStream_t s2;
    cudaStreamCreateWithFlags(&s2, cudaStreamNonBlocking);
    cudaEvent_t evF, evP, evJ;
    cudaEventCreateWithFlags(&evF, cudaEventDisableTiming);
    cudaEventCreateWithFlags(&evP, cudaEventDisableTiming);
    cudaEventCreateWithFlags(&evJ, cudaEventDisableTiming);

    // side: weight prep (tiny) -> evP; then fill + dis -> evJ
    cudaEventRecord(evF, 0);
    cudaStreamWaitEvent(s2, evF, 0);
    k_prepW<<<(IN_DIM * H1 + 255) / 256, 256, 0, s2>>>(W1, W2, W1h, W2h);
    cudaEventRecord(evP, s2);
    k_fill<<<(N_EDGES / 4 + 255) / 256, 256, 0, s2>>>(row, col, cnt, crow);
    k_dis<<<(N_NODES + 255) / 256, 256, 0, s2>>>(cnt, deg, dis);
    cudaEventRecord(evJ, s2);

    // main: GEMM1 (fp16, B-resident) after W1h ready
    cudaStreamWaitEvent(0, evP, 0);
    k_gemm1_f16<<<(N_NODES + 127) / 128, 512, G1_SMEM>>>(x, W1h, h1, N_NODES);

    // join; gather1 (+b1+relu) -> agg1
    cudaStreamWaitEvent(0, evJ, 0);
    k_gather128<<<(N_NODES * 32 + 255) / 256, 256>>>(h1, agg1, deg, crow, dis, b1);

    // GEMM2
    k_gemm2_f16<<<(N_NODES + 127) / 128, 256, G2_SMEM>>>(agg1, W2h, h2, N_NODES);

    // gather2 + pool, FC
    k_gather64pool<<<(N_NODES * 32 + 255) / 256, 256>>>(h2, deg, crow, dis, b2, batch, pool);
    k_fc<<<1, 128>>>(pool, Wfc, bfc, out);
}